// round 3
// baseline (speedup 1.0000x reference)
#include <cuda_runtime.h>
#include <cuda_bf16.h>
#include <cstdint>
#include <cstddef>

// ---------------- problem dims ----------------
#define BB 4096   // batch tokens
#define DD 1024   // input dim
#define HH 4096   // hidden
#define OO 1024   // output dim
#define NE 8      // experts
#define NAE 5     // active experts

// ---------------- device scratch (no cudaMalloc allowed) ----------------
__device__ __nv_bfloat16 g_x2[(size_t)BB * 2 * DD];              // x split [hi|lo]
__device__ __nv_bfloat16 g_w1s[(size_t)NE * HH * 2 * DD];        // W1 split
__device__ __nv_bfloat16 g_w2s[(size_t)NE * OO * 2 * HH];        // W2 split
__device__ __nv_bfloat16 g_hs[(size_t)NE * BB * 2 * HH];         // per-expert gw-scaled h split
__device__ float g_gw[(size_t)BB * NE];                          // gate weights

// ---------------- helpers ----------------
__device__ __forceinline__ uint32_t smem_u32(const void* p) {
    uint32_t a;
    asm("{ .reg .u64 t; cvta.to.shared.u64 t, %1; cvt.u32.u64 %0, t; }" : "=r"(a) : "l"(p));
    return a;
}
#define SWZ(off) ((off) ^ (((off) >> 3) & 0x70))

__device__ __forceinline__ void cp_async16(uint32_t saddr, const void* gptr) {
    asm volatile("cp.async.cg.shared.global [%0], [%1], 16;\n" :: "r"(saddr), "l"(gptr));
}
__device__ __forceinline__ void cp_commit() {
    asm volatile("cp.async.commit_group;\n" ::: "memory");
}
template <int N>
__device__ __forceinline__ void cp_wait() {
    asm volatile("cp.async.wait_group %0;\n" :: "n"(N) : "memory");
}
__device__ __forceinline__ void ldsm_x4(uint32_t& r0, uint32_t& r1, uint32_t& r2,
                                        uint32_t& r3, uint32_t addr) {
    asm volatile("ldmatrix.sync.aligned.m8n8.x4.shared.b16 {%0,%1,%2,%3}, [%4];"
                 : "=r"(r0), "=r"(r1), "=r"(r2), "=r"(r3) : "r"(addr));
}
__device__ __forceinline__ void mma16816(float* c, const uint32_t* a, const uint32_t* b) {
    asm volatile(
        "mma.sync.aligned.m16n8k16.row.col.f32.bf16.bf16.f32 "
        "{%0,%1,%2,%3}, {%4,%5,%6,%7}, {%8,%9}, {%0,%1,%2,%3};"
        : "+f"(c[0]), "+f"(c[1]), "+f"(c[2]), "+f"(c[3])
        : "r"(a[0]), "r"(a[1]), "r"(a[2]), "r"(a[3]), "r"(b[0]), "r"(b[1]));
}

// ---------------- gate kernel ----------------
__global__ void gate_kernel(const float* __restrict__ x, const float* __restrict__ Wg,
                            const float* __restrict__ bg, float* __restrict__ gw) {
    __shared__ float slog[NE];
    int b = blockIdx.x;
    int wid = threadIdx.x >> 5, lid = threadIdx.x & 31;
    const float* xr = x + (size_t)b * DD;
    const float* wr = Wg + (size_t)wid * DD;
    float s = 0.f;
    for (int i = lid; i < DD; i += 32) s += xr[i] * wr[i];
#pragma unroll
    for (int o = 16; o > 0; o >>= 1) s += __shfl_xor_sync(0xffffffffu, s, o);
    if (lid == 0) slog[wid] = s + bg[wid];
    __syncthreads();
    if (threadIdx.x == 0) {
        const float invT = 0.36787944117144233f;  // 1/e
        float l[NE], mx = -1e30f;
#pragma unroll
        for (int i = 0; i < NE; i++) { l[i] = slog[i] * invT; mx = fmaxf(mx, l[i]); }
        float p[NE], se = 0.f;
#pragma unroll
        for (int i = 0; i < NE; i++) { p[i] = expf(l[i] - mx); se += p[i]; }
        float inv_se = 1.f / se;
#pragma unroll
        for (int i = 0; i < NE; i++) p[i] *= inv_se;
        bool sel[NE];
#pragma unroll
        for (int i = 0; i < NE; i++) sel[i] = false;
        float ss = 0.f;
        for (int it = 0; it < NAE; it++) {
            int bi = 0; float bv = -1.f;
#pragma unroll
            for (int i = 0; i < NE; i++)
                if (!sel[i] && p[i] > bv) { bv = p[i]; bi = i; }
            sel[bi] = true; ss += bv;
        }
        float inv = 1.f / (ss + 1e-8f);
#pragma unroll
        for (int i = 0; i < NE; i++)
            gw[(size_t)b * NE + i] = sel[i] ? p[i] * inv : 0.f;
    }
}

// ---------------- fp32 -> bf16 hi/lo split: in[R][K] -> out[R][2K] ----------------
__global__ void split_kernel(const float* __restrict__ in, __nv_bfloat16* __restrict__ out,
                             int K, size_t total) {
    size_t n4 = total >> 2;
    size_t i = (size_t)blockIdx.x * blockDim.x + threadIdx.x;
    size_t str = (size_t)gridDim.x * blockDim.x;
    for (; i < n4; i += str) {
        size_t idx = i << 2;
        size_t r = idx / (size_t)K;
        int c = (int)(idx - r * (size_t)K);
        float4 v = reinterpret_cast<const float4*>(in)[i];
        float vv[4] = {v.x, v.y, v.z, v.w};
        __nv_bfloat16 hb[4], lb[4];
#pragma unroll
        for (int j = 0; j < 4; j++) {
            hb[j] = __float2bfloat16(vv[j]);
            lb[j] = __float2bfloat16(vv[j] - __bfloat162float(hb[j]));
        }
        size_t base = r * (size_t)(2 * K) + c;
        *reinterpret_cast<uint2*>(out + base)     = *reinterpret_cast<uint2*>(hb);
        *reinterpret_cast<uint2*>(out + base + K) = *reinterpret_cast<uint2*>(lb);
    }
}

// ---------------- shared GEMM tile config ----------------
#define BM 128
#define BN 128
#define BK 64
#define TPB 256
#define STAGE 16384                     // 128 rows x 128 bytes
#define SMEM1 (4 * STAGE)
#define SMEM2 (4 * STAGE + 8 * BN * 4 + BM * 8 * 4)

// ===================== layer-1 GEMM =====================
// h_z = gw[:,z] * relu(x @ W1_z^T + b1_z), hi/lo split -> g_hs[z]
__global__ __launch_bounds__(TPB) void gemm1_kernel(
    const __nv_bfloat16* __restrict__ A,          // x2 [BB][2*DD]
    const __nv_bfloat16* __restrict__ Wbase,      // w1s [NE][HH][2*DD]
    const float* __restrict__ b1,                 // [NE][HH]
    const float* __restrict__ gw,                 // [BB][NE]
    __nv_bfloat16* __restrict__ hsBase) {         // [NE][BB][2*HH]
    extern __shared__ __align__(1024) char smem[];
    uint32_t sbase = smem_u32(smem);
    int tid = threadIdx.x, lid = tid & 31, wid = tid >> 5;
    int warp_m = wid >> 2, warp_n = wid & 3;
    int m0 = blockIdx.y * BM, n0 = blockIdx.x * BN;
    int z = blockIdx.z;
    const int ld = 2 * DD;
    const int KC = DD / BK;        // 16
    const int NC = 3 * KC;         // 48

    const __nv_bfloat16* Bm = Wbase + (size_t)z * HH * ld;
    const float* bias = b1 + (size_t)z * HH;

    float acc[4][4][4];
#pragma unroll
    for (int a = 0; a < 4; a++)
#pragma unroll
        for (int b = 0; b < 4; b++)
#pragma unroll
            for (int c = 0; c < 4; c++) acc[a][b][c] = 0.f;

    auto load_chunk = [&](int ci, int s) {
        int t = ci / KC, rem = ci - t * KC;
        int acol = (t == 2 ? DD : 0) + rem * BK;
        int bcol = (t == 1 ? DD : 0) + rem * BK;
        const __nv_bfloat16* Ab = A + (size_t)m0 * ld + acol;
        const __nv_bfloat16* Bb = Bm + (size_t)n0 * ld + bcol;
        uint32_t sa = sbase + s * STAGE;
        uint32_t sb = sbase + 2 * STAGE + s * STAGE;
#pragma unroll
        for (int i = 0; i < 4; i++) {
            int u = tid + i * TPB;
            int r = u >> 3, seg = u & 7;
            uint32_t off = SWZ((uint32_t)(r * 128 + seg * 16));
            cp_async16(sa + off, Ab + (size_t)r * ld + seg * 8);
            cp_async16(sb + off, Bb + (size_t)r * ld + seg * 8);
        }
    };
    auto compute_stage = [&](int s) {
        uint32_t saA = sbase + s * STAGE;
        uint32_t saB = sbase + 2 * STAGE + s * STAGE;
        int rA = warp_m * 64 + (lid & 15);
        int rB = warp_n * 32 + (lid & 15);
        int kb = (lid >> 4) * 16;
#pragma unroll
        for (int ks = 0; ks < 4; ks++) {
            int colb = ks * 32 + kb;
            uint32_t a[4][4];
#pragma unroll
            for (int mf = 0; mf < 4; mf++) {
                uint32_t addr = saA + SWZ((uint32_t)((rA + mf * 16) * 128 + colb));
                ldsm_x4(a[mf][0], a[mf][1], a[mf][2], a[mf][3], addr);
            }
            uint32_t b[4][2];
#pragma unroll
            for (int pr = 0; pr < 2; pr++) {
                uint32_t r0, r1, r2, r3;
                uint32_t addr = saB + SWZ((uint32_t)((rB + pr * 16) * 128 + colb));
                ldsm_x4(r0, r1, r2, r3, addr);
                b[pr * 2 + 0][0] = r0; b[pr * 2 + 1][0] = r1;
                b[pr * 2 + 0][1] = r2; b[pr * 2 + 1][1] = r3;
            }
#pragma unroll
            for (int mf = 0; mf < 4; mf++)
#pragma unroll
                for (int nf = 0; nf < 4; nf++)
                    mma16816(acc[mf][nf], a[mf], b[nf]);
        }
    };

    load_chunk(0, 0);
    cp_commit();
    for (int ci = 0; ci < NC; ci++) {
        int s = ci & 1;
        if (ci + 1 < NC) {
            load_chunk(ci + 1, (ci + 1) & 1);
            cp_commit();
            cp_wait<1>();
        } else {
            cp_wait<0>();
        }
        __syncthreads();
        compute_stage(s);
        __syncthreads();
    }

    // epilogue: gw-scale + relu + split
    int g = lid >> 2, t4 = lid & 3;
    __nv_bfloat16* hs = hsBase + (size_t)z * BB * (2 * HH);
#pragma unroll
    for (int mf = 0; mf < 4; mf++) {
#pragma unroll
        for (int h = 0; h < 2; h++) {
            int row = m0 + warp_m * 64 + mf * 16 + g + h * 8;
            float wv = gw[(size_t)row * NE + z];
#pragma unroll
            for (int nf = 0; nf < 4; nf++) {
                int col = n0 + warp_n * 32 + nf * 8 + t4 * 2;
                float2 bz = *reinterpret_cast<const float2*>(bias + col);
                float v0 = fmaxf(acc[mf][nf][h * 2 + 0] + bz.x, 0.f) * wv;
                float v1 = fmaxf(acc[mf][nf][h * 2 + 1] + bz.y, 0.f) * wv;
                __nv_bfloat16 h0 = __float2bfloat16(v0);
                __nv_bfloat16 h1 = __float2bfloat16(v1);
                __nv_bfloat16 l0 = __float2bfloat16(v0 - __bfloat162float(h0));
                __nv_bfloat16 l1 = __float2bfloat16(v1 - __bfloat162float(h1));
                uint32_t hp = ((uint32_t)__bfloat16_as_ushort(h1) << 16) |
                              (uint32_t)__bfloat16_as_ushort(h0);
                uint32_t lp = ((uint32_t)__bfloat16_as_ushort(l1) << 16) |
                              (uint32_t)__bfloat16_as_ushort(l0);
                size_t base = (size_t)row * (2 * HH) + col;
                *reinterpret_cast<uint32_t*>(hs + base) = hp;
                *reinterpret_cast<uint32_t*>(hs + base + HH) = lp;
            }
        }
    }
}

// ===================== layer-2 GEMM (merged experts, race-free) =====================
// out[b,o] = sum_z (gw_z*h_z) @ W2_z^T  +  sum_z gw[b,z]*b2[z,o]
__global__ __launch_bounds__(TPB) void gemm2_kernel(
    const __nv_bfloat16* __restrict__ hsBase,     // [NE][BB][2*HH]
    const __nv_bfloat16* __restrict__ Wbase,      // w2s [NE][OO][2*HH]
    const float* __restrict__ b2,                 // [NE][OO]
    const float* __restrict__ gw,                 // [BB][NE]
    float* __restrict__ out) {                    // [BB][OO]
    extern __shared__ __align__(1024) char smem[];
    uint32_t sbase = smem_u32(smem);
    float* b2s = reinterpret_cast<float*>(smem + 4 * STAGE);            // [NE][BN]
    float* gws = reinterpret_cast<float*>(smem + 4 * STAGE + 8 * BN * 4); // [BM][NE]
    int tid = threadIdx.x, lid = tid & 31, wid = tid >> 5;
    int warp_m = wid >> 2, warp_n = wid & 3;
    int m0 = blockIdx.y * BM, n0 = blockIdx.x * BN;
    const int ld = 2 * HH;
    const int KC = HH / BK;           // 64
    const int NCZ = 3 * KC;           // 192 per expert
    const int NC = NE * NCZ;          // 1536

    // stage bias + gate rows
    for (int i = tid; i < NE * BN; i += TPB) {
        int zz = i / BN, c = i - zz * BN;
        b2s[i] = b2[(size_t)zz * OO + n0 + c];
    }
    for (int i = tid; i < BM * NE; i += TPB) {
        int r = i >> 3, zz = i & 7;
        gws[i] = gw[(size_t)(m0 + r) * NE + zz];
    }

    float acc[4][4][4];
#pragma unroll
    for (int a = 0; a < 4; a++)
#pragma unroll
        for (int b = 0; b < 4; b++)
#pragma unroll
            for (int c = 0; c < 4; c++) acc[a][b][c] = 0.f;

    auto load_chunk = [&](int ci, int s) {
        int z = ci / NCZ;
        int w = ci - z * NCZ;
        int t = w / KC, rem = w - t * KC;
        int acol = (t == 2 ? HH : 0) + rem * BK;
        int bcol = (t == 1 ? HH : 0) + rem * BK;
        const __nv_bfloat16* Ab = hsBase + (size_t)z * BB * ld + (size_t)m0 * ld + acol;
        const __nv_bfloat16* Bb = Wbase + (size_t)z * OO * ld + (size_t)n0 * ld + bcol;
        uint32_t sa = sbase + s * STAGE;
        uint32_t sb = sbase + 2 * STAGE + s * STAGE;
#pragma unroll
        for (int i = 0; i < 4; i++) {
            int u = tid + i * TPB;
            int r = u >> 3, seg = u & 7;
            uint32_t off = SWZ((uint32_t)(r * 128 + seg * 16));
            cp_async16(sa + off, Ab + (size_t)r * ld + seg * 8);
            cp_async16(sb + off, Bb + (size_t)r * ld + seg * 8);
        }
    };
    auto compute_stage = [&](int s) {
        uint32_t saA = sbase + s * STAGE;
        uint32_t saB = sbase + 2 * STAGE + s * STAGE;
        int rA = warp_m * 64 + (lid & 15);
        int rB = warp_n * 32 + (lid & 15);
        int kb = (lid >> 4) * 16;
#pragma unroll
        for (int ks = 0; ks < 4; ks++) {
            int colb = ks * 32 + kb;
            uint32_t a[4][4];
#pragma unroll
            for (int mf = 0; mf < 4; mf++) {
                uint32_t addr = saA + SWZ((uint32_t)((rA + mf * 16) * 128 + colb));
                ldsm_x4(a[mf][0], a[mf][1], a[mf][2], a[mf][3], addr);
            }
            uint32_t b[4][2];
#pragma unroll
            for (int pr = 0; pr < 2; pr++) {
                uint32_t r0, r1, r2, r3;
                uint32_t addr = saB + SWZ((uint32_t)((rB + pr * 16) * 128 + colb));
                ldsm_x4(r0, r1, r2, r3, addr);
                b[pr * 2 + 0][0] = r0; b[pr * 2 + 1][0] = r1;
                b[pr * 2 + 0][1] = r2; b[pr * 2 + 1][1] = r3;
            }
#pragma unroll
            for (int mf = 0; mf < 4; mf++)
#pragma unroll
                for (int nf = 0; nf < 4; nf++)
                    mma16816(acc[mf][nf], a[mf], b[nf]);
        }
    };

    load_chunk(0, 0);
    cp_commit();
    for (int ci = 0; ci < NC; ci++) {
        int s = ci & 1;
        if (ci + 1 < NC) {
            load_chunk(ci + 1, (ci + 1) & 1);
            cp_commit();
            cp_wait<1>();
        } else {
            cp_wait<0>();
        }
        __syncthreads();
        compute_stage(s);
        __syncthreads();
    }

    // epilogue: add sum_z gw*b2, single write
    int g = lid >> 2, t4 = lid & 3;
#pragma unroll
    for (int mf = 0; mf < 4; mf++) {
#pragma unroll
        for (int h = 0; h < 2; h++) {
            int row_l = warp_m * 64 + mf * 16 + g + h * 8;
            int row = m0 + row_l;
            float gwr[NE];
#pragma unroll
            for (int zz = 0; zz < NE; zz++) gwr[zz] = gws[row_l * NE + zz];
#pragma unroll
            for (int nf = 0; nf < 4; nf++) {
                int col_l = warp_n * 32 + nf * 8 + t4 * 2;
                float bs0 = 0.f, bs1 = 0.f;
#pragma unroll
                for (int zz = 0; zz < NE; zz++) {
                    bs0 += gwr[zz] * b2s[zz * BN + col_l];
                    bs1 += gwr[zz] * b2s[zz * BN + col_l + 1];
                }
                float2 o;
                o.x = acc[mf][nf][h * 2 + 0] + bs0;
                o.y = acc[mf][nf][h * 2 + 1] + bs1;
                *reinterpret_cast<float2*>(out + (size_t)row * OO + n0 + col_l) = o;
            }
        }
    }
}

// ---------------- host launcher ----------------
extern "C" void kernel_launch(void* const* d_in, const int* in_sizes, int n_in,
                              void* d_out, int out_size) {
    const float* x  = (const float*)d_in[0];
    const float* W1 = (const float*)d_in[1];
    const float* b1 = (const float*)d_in[2];
    const float* W2 = (const float*)d_in[3];
    const float* b2 = (const float*)d_in[4];
    const float* Wg = (const float*)d_in[5];
    const float* bg = (const float*)d_in[6];
    float* out = (float*)d_out;

    void *px2, *pw1s, *pw2s, *phs, *pgw;
    cudaGetSymbolAddress(&px2, g_x2);
    cudaGetSymbolAddress(&pw1s, g_w1s);
    cudaGetSymbolAddress(&pw2s, g_w2s);
    cudaGetSymbolAddress(&phs, g_hs);
    cudaGetSymbolAddress(&pgw, g_gw);

    cudaFuncSetAttribute(gemm1_kernel, cudaFuncAttributeMaxDynamicSharedMemorySize, SMEM1);
    cudaFuncSetAttribute(gemm2_kernel, cudaFuncAttributeMaxDynamicSharedMemorySize, SMEM2);

    gate_kernel<<<BB, 256>>>(x, Wg, bg, (float*)pgw);
    split_kernel<<<4096, 256>>>(x, (__nv_bfloat16*)px2, DD, (size_t)BB * DD);
    split_kernel<<<16384, 256>>>(W1, (__nv_bfloat16*)pw1s, DD, (size_t)NE * HH * DD);
    split_kernel<<<16384, 256>>>(W2, (__nv_bfloat16*)pw2s, HH, (size_t)NE * OO * HH);

    // layer 1 (all experts): h_z = gw_z * relu(x @ W1_z^T + b1_z) -> split into g_hs
    gemm1_kernel<<<dim3(HH / BN, BB / BM, NE), TPB, SMEM1>>>(
        (const __nv_bfloat16*)px2, (const __nv_bfloat16*)pw1s, b1,
        (const float*)pgw, (__nv_bfloat16*)phs);

    // layer 2 (merged experts): out = sum_z h_z @ W2_z^T + sum_z gw_z*b2_z
    gemm2_kernel<<<dim3(OO / BN, BB / BM), TPB, SMEM2>>>(
        (const __nv_bfloat16*)phs, (const __nv_bfloat16*)pw2s, b2,
        (const float*)pgw, out);
}